// round 1
// baseline (speedup 1.0000x reference)
#include <cuda_runtime.h>
#include <cstdint>
#include <cstddef>

#define EPSV 1e-5f

// ---------------- scratch (static device memory; no allocation at runtime) ----
__device__ float g_xyz [16*2048*3];
__device__ float g_xyz1[16*512*3];
__device__ float g_xyz2[16*256*3];
__device__ float g_f0  [16*2048*64];   // emb1 raw (pre-BN) output
__device__ float g_f1r [16*2048*64];   // emb2 raw (pre-BN) output
__device__ float g_feat1[16*512*128];  // stage1 final features
__device__ int   g_fps1[16*512];
__device__ int   g_fps2[16*256];
__device__ int   g_knn1[16*512*32];
__device__ int   g_knn2[16*256*32];
__device__ float g_sum[512];
__device__ float g_sq [512];
__device__ float g_ab [1024];          // [a(0..C-1), b(0..C-1)]
__device__ float g_bufA[67108864];     // 256 MB scratch
__device__ float g_bufB[67108864];     // 256 MB scratch

// ---------------- tiny helpers ----------------------------------------------
__global__ void zero_kernel(float* s, float* q, int C) {
    int c = threadIdx.x;
    if (c < C) { s[c] = 0.f; q[c] = 0.f; }
}

__global__ void bn_finalize(const float* __restrict__ sum, const float* __restrict__ sq,
                            const float* __restrict__ gamma, const float* __restrict__ beta,
                            float inv_count, int C, float* __restrict__ ab)
{
    int c = threadIdx.x;
    if (c < C) {
        float m = sum[c] * inv_count;
        float v = sq[c] * inv_count - m * m;
        v = fmaxf(v, 0.f);
        float a = gamma[c] * rsqrtf(v + EPSV);
        ab[c] = a;
        ab[C + c] = beta[c] - m * a;
    }
}

// ---------------- emb1: transpose + [32768,3]x[3,64] + stats ----------------
__global__ void emb1_kernel(const float* __restrict__ x, const float* __restrict__ w,
                            float* __restrict__ xyz, float* __restrict__ f0,
                            float* __restrict__ sum, float* __restrict__ sq)
{
    __shared__ float ws[192];
    __shared__ float csum[64], csq[64];
    int tid = threadIdx.x;
    if (tid < 192) ws[tid] = w[tid];
    if (tid < 64) { csum[tid] = 0.f; csq[tid] = 0.f; }
    __syncthreads();
    int p = blockIdx.x * 256 + tid;            // point 0..32767
    int b = p >> 11, n = p & 2047;
    float X = x[(b*3+0)*2048 + n];
    float Y = x[(b*3+1)*2048 + n];
    float Z = x[(b*3+2)*2048 + n];
    xyz[p*3+0] = X; xyz[p*3+1] = Y; xyz[p*3+2] = Z;
    int lane = tid & 31;
    for (int o = 0; o < 64; o++) {
        float y = X*ws[o*3] + Y*ws[o*3+1] + Z*ws[o*3+2];
        f0[(size_t)p*64 + o] = y;
        float t = y, t2 = y*y;
        #pragma unroll
        for (int off = 16; off > 0; off >>= 1) {
            t  += __shfl_xor_sync(0xffffffffu, t,  off);
            t2 += __shfl_xor_sync(0xffffffffu, t2, off);
        }
        if (lane == 0) { atomicAdd(&csum[o], t); atomicAdd(&csq[o], t2); }
    }
    __syncthreads();
    if (tid < 64) { atomicAdd(&sum[tid], csum[tid]); atomicAdd(&sq[tid], csq[tid]); }
}

// ---------------- generic SGEMM: C = bnrelu?(A) * W^T + bias, + channel stats -
// A:[M,K] row-major, W:[N,K] row-major, C:[M,N]. bnA: [2K] (a,b) applied to A
// with relu on load; bias may be null. Accumulates per-column sum/sumsq of C.
template<int BM, int BN, int BK, int TM, int TN>
__global__ void __launch_bounds__(256, 2) gemm_bn_kernel(
    const float* __restrict__ A, const float* __restrict__ W,
    const float* __restrict__ bias, const float* __restrict__ bnA,
    float* __restrict__ C, int M, int N, int K,
    float* __restrict__ sum, float* __restrict__ sq)
{
    constexpr int NTX = BN / TN;
    __shared__ __align__(16) float As[BK][BM + 4];
    __shared__ __align__(16) float Ws[BK][BN + 4];
    __shared__ float csum[BN], csq[BN];
    int tid = threadIdx.x;
    int tx = tid % NTX, ty = tid / NTX;
    int m0 = blockIdx.x * BM, n0 = blockIdx.y * BN;
    if (tid < BN) { csum[tid] = 0.f; csq[tid] = 0.f; }

    float acc[TM][TN];
    #pragma unroll
    for (int i = 0; i < TM; i++)
        #pragma unroll
        for (int j = 0; j < TN; j++) acc[i][j] = 0.f;

    const int lrow = tid / (BK/4);
    const int lcol = (tid % (BK/4)) * 4;
    constexpr int ROWSTEP = 256 / (BK/4);   // 64

    for (int k0 = 0; k0 < K; k0 += BK) {
        #pragma unroll
        for (int r = 0; r < BM; r += ROWSTEP) {
            float4 v = *reinterpret_cast<const float4*>(&A[(size_t)(m0 + r + lrow)*K + k0 + lcol]);
            if (bnA) {
                v.x = fmaxf(bnA[k0+lcol+0]*v.x + bnA[K + k0+lcol+0], 0.f);
                v.y = fmaxf(bnA[k0+lcol+1]*v.y + bnA[K + k0+lcol+1], 0.f);
                v.z = fmaxf(bnA[k0+lcol+2]*v.z + bnA[K + k0+lcol+2], 0.f);
                v.w = fmaxf(bnA[k0+lcol+3]*v.w + bnA[K + k0+lcol+3], 0.f);
            }
            As[lcol+0][r+lrow] = v.x;
            As[lcol+1][r+lrow] = v.y;
            As[lcol+2][r+lrow] = v.z;
            As[lcol+3][r+lrow] = v.w;
        }
        #pragma unroll
        for (int r = 0; r < BN; r += ROWSTEP) {
            float4 v = *reinterpret_cast<const float4*>(&W[(size_t)(n0 + r + lrow)*K + k0 + lcol]);
            Ws[lcol+0][r+lrow] = v.x;
            Ws[lcol+1][r+lrow] = v.y;
            Ws[lcol+2][r+lrow] = v.z;
            Ws[lcol+3][r+lrow] = v.w;
        }
        __syncthreads();
        #pragma unroll
        for (int kk = 0; kk < BK; kk++) {
            float af[TM], wf[TN];
            #pragma unroll
            for (int i = 0; i < TM; i += 4) {
                float4 t = *reinterpret_cast<const float4*>(&As[kk][ty*TM + i]);
                af[i] = t.x; af[i+1] = t.y; af[i+2] = t.z; af[i+3] = t.w;
            }
            #pragma unroll
            for (int j = 0; j < TN; j += 4) {
                float4 t = *reinterpret_cast<const float4*>(&Ws[kk][tx*TN + j]);
                wf[j] = t.x; wf[j+1] = t.y; wf[j+2] = t.z; wf[j+3] = t.w;
            }
            #pragma unroll
            for (int i = 0; i < TM; i++)
                #pragma unroll
                for (int j = 0; j < TN; j++)
                    acc[i][j] = fmaf(af[i], wf[j], acc[i][j]);
        }
        __syncthreads();
    }

    // epilogue: bias, stats, store
    #pragma unroll
    for (int j = 0; j < TN; j++) {
        int n = n0 + tx*TN + j;
        float bsv = bias ? bias[n] : 0.f;
        float s_ = 0.f, q_ = 0.f;
        #pragma unroll
        for (int i = 0; i < TM; i++) {
            float y = acc[i][j] + bsv;
            acc[i][j] = y;
            s_ += y; q_ += y*y;
        }
        atomicAdd(&csum[tx*TN + j], s_);
        atomicAdd(&csq [tx*TN + j], q_);
    }
    #pragma unroll
    for (int i = 0; i < TM; i++) {
        #pragma unroll
        for (int j = 0; j < TN; j += 4) {
            float4 v = make_float4(acc[i][j], acc[i][j+1], acc[i][j+2], acc[i][j+3]);
            *reinterpret_cast<float4*>(&C[(size_t)(m0 + ty*TM + i)*N + n0 + tx*TN + j]) = v;
        }
    }
    __syncthreads();
    if (tid < BN) {
        atomicAdd(&sum[n0 + tid], csum[tid]);
        atomicAdd(&sq [n0 + tid], csq[tid]);
    }
}

// ---------------- farthest point sampling (one block per batch) --------------
__global__ void fps_kernel(const float* __restrict__ xyz, int N, int S,
                           int* __restrict__ idx_out, float* __restrict__ xyz_out)
{
    __shared__ float px[2048], py[2048], pz[2048], dist[2048];
    __shared__ float rv[256];
    __shared__ int   ri[256];
    __shared__ int   sidx[512];
    int b = blockIdx.x, tid = threadIdx.x;
    for (int i = tid; i < N; i += 256) {
        px[i] = xyz[(b*N + i)*3 + 0];
        py[i] = xyz[(b*N + i)*3 + 1];
        pz[i] = xyz[(b*N + i)*3 + 2];
        dist[i] = 1e10f;
    }
    __syncthreads();
    int sel = 0;
    for (int it = 0; it < S; it++) {
        if (tid == 0) sidx[it] = sel;
        float sx = px[sel], sy = py[sel], sz = pz[sel];
        float bv = -1.f; int bi = 0;
        for (int j = tid; j < N; j += 256) {
            float dx = px[j]-sx, dy = py[j]-sy, dz = pz[j]-sz;
            float d = dx*dx + dy*dy + dz*dz;
            float nd = fminf(dist[j], d);
            dist[j] = nd;
            if (nd > bv) { bv = nd; bi = j; }   // strict > keeps lowest j per thread
        }
        rv[tid] = bv; ri[tid] = bi;
        __syncthreads();
        #pragma unroll
        for (int off = 128; off > 0; off >>= 1) {
            if (tid < off) {
                float ov = rv[tid+off]; int oi = ri[tid+off];
                if (ov > rv[tid] || (ov == rv[tid] && oi < ri[tid])) { rv[tid] = ov; ri[tid] = oi; }
            }
            __syncthreads();
        }
        sel = ri[0];
        __syncthreads();
    }
    for (int s = tid; s < S; s += 256) {
        int i = sidx[s];
        idx_out[b*S + s] = i;
        xyz_out[(b*S + s)*3 + 0] = px[i];
        xyz_out[(b*S + s)*3 + 1] = py[i];
        xyz_out[(b*S + s)*3 + 2] = pz[i];
    }
}

// ---------------- kNN (k=32): one warp per query, one slot per lane ----------
__global__ void knn_kernel(const float* __restrict__ q_xyz, const float* __restrict__ c_xyz,
                           int S, int N, int* __restrict__ knn)
{
    __shared__ float cx[2048], cy[2048], cz[2048];
    int b = blockIdx.y, tid = threadIdx.x;
    for (int i = tid; i < N; i += blockDim.x) {
        cx[i] = c_xyz[(b*N + i)*3 + 0];
        cy[i] = c_xyz[(b*N + i)*3 + 1];
        cz[i] = c_xyz[(b*N + i)*3 + 2];
    }
    __syncthreads();
    int warp = tid >> 5, lane = tid & 31;
    int q = blockIdx.x * (blockDim.x >> 5) + warp;
    if (q >= S) return;
    float qx = q_xyz[(b*S+q)*3+0], qy = q_xyz[(b*S+q)*3+1], qz = q_xyz[(b*S+q)*3+2];
    float topd = 3.4e38f; int topi = 0;
    float curmax = 3.4e38f;
    for (int c0 = 0; c0 < N; c0 += 32) {
        int c = c0 + lane;
        float dx = cx[c]-qx, dy = cy[c]-qy, dz = cz[c]-qz;
        float d = dx*dx + dy*dy + dz*dz;
        unsigned bal = __ballot_sync(0xffffffffu, d < curmax);
        while (bal) {
            int src = __ffs(bal) - 1; bal &= bal - 1;
            float dv = __shfl_sync(0xffffffffu, d, src);
            // warp argmax of topd (deterministic tie-break by lane)
            float mv = topd; int ml = lane;
            #pragma unroll
            for (int off = 16; off > 0; off >>= 1) {
                float ov = __shfl_xor_sync(0xffffffffu, mv, off);
                int   ol = __shfl_xor_sync(0xffffffffu, ml, off);
                if (ov > mv || (ov == mv && ol < ml)) { mv = ov; ml = ol; }
            }
            if (dv < mv && lane == ml) { topd = dv; topi = c0 + src; }
            curmax = mv;  // monotone upper bound of current max
        }
    }
    knn[(b*S + q)*32 + lane] = topi;
}

// ---------------- gather/aggregate -------------------------------------------
// stage1: apply emb2 BN+relu on the fly; agg rows [b*512+s, k] of 128 channels
__global__ void gather1_kernel(const float* __restrict__ f1raw, const int* __restrict__ fps,
                               const int* __restrict__ knn, const float* __restrict__ ab,
                               float* __restrict__ agg)
{
    int bs = blockIdx.x;           // b*512+s
    int b = bs >> 9;
    __shared__ float ctr[64];
    int tid = threadIdx.x;
    if (tid < 64) {
        int ci = fps[bs];
        float v = f1raw[(size_t)(b*2048 + ci)*64 + tid];
        ctr[tid] = fmaxf(ab[tid]*v + ab[64+tid], 0.f);
    }
    __syncthreads();
    for (int e = tid; e < 32*64; e += 256) {
        int k = e >> 6, c = e & 63;
        int ni = knn[bs*32 + k];
        float v = f1raw[(size_t)(b*2048 + ni)*64 + c];
        v = fmaxf(ab[c]*v + ab[64+c], 0.f);
        size_t row = (size_t)bs*32 + k;
        agg[row*128 + c]      = v - ctr[c];
        agg[row*128 + 64 + c] = ctr[c];
    }
}

// stage2: features already final; agg rows [b*256+s, k] of 256 channels
__global__ void gather2_kernel(const float* __restrict__ feat, const int* __restrict__ fps,
                               const int* __restrict__ knn, float* __restrict__ agg)
{
    int bs = blockIdx.x;           // b*256+s
    int b = bs >> 8;
    __shared__ float ctr[128];
    int tid = threadIdx.x;
    if (tid < 128) {
        int ci = fps[bs];
        ctr[tid] = feat[(size_t)(b*512 + ci)*128 + tid];
    }
    __syncthreads();
    for (int e = tid; e < 32*128; e += 256) {
        int k = e >> 7, c = e & 127;
        int ni = knn[bs*32 + k];
        float v = feat[(size_t)(b*512 + ni)*128 + c];
        size_t row = (size_t)bs*32 + k;
        agg[row*256 + c]       = v - ctr[c];
        agg[row*256 + 128 + c] = ctr[c];
    }
}

// ---------------- fused BN+relu+max over k ----------------------------------
// extreme = max if a>=0 else min (relu(a*x+b) monotone in x)
__global__ void maxk_kernel(const float* __restrict__ h, const float* __restrict__ ab,
                            float* __restrict__ out, int C)
{
    int idx = blockIdx.x * blockDim.x + threadIdx.x;   // q*C + o
    int q = idx / C, o = idx - q*C;
    float mx = -3.4e38f, mn = 3.4e38f;
    for (int k = 0; k < 32; k++) {
        float v = h[(size_t)(q*32 + k)*C + o];
        mx = fmaxf(mx, v); mn = fminf(mn, v);
    }
    float a = ab[o];
    float e = (a >= 0.f) ? mx : mn;
    out[idx] = fmaxf(a*e + ab[C+o], 0.f);
}

// final: also transpose to [B, 512, 256]
__global__ void final_max_kernel(const float* __restrict__ h, const float* __restrict__ ab,
                                 float* __restrict__ out)
{
    int idx = blockIdx.x * blockDim.x + threadIdx.x;  // 16*256*512
    int o = idx & 511; int q = idx >> 9; int b = q >> 8, s = q & 255;
    float mx = -3.4e38f, mn = 3.4e38f;
    for (int k = 0; k < 32; k++) {
        float v = h[(size_t)(q*32 + k)*512 + o];
        mx = fmaxf(mx, v); mn = fminf(mn, v);
    }
    float a = ab[o];
    float e = (a >= 0.f) ? mx : mn;
    out[(size_t)(b*512 + o)*256 + s] = fmaxf(a*e + ab[512+o], 0.f);
}

// ---------------- driver ------------------------------------------------------
extern "C" void kernel_launch(void* const* d_in, const int* in_sizes, int n_in,
                              void* d_out, int out_size)
{
    const float* x       = (const float*)d_in[0];
    const float* emb_w1  = (const float*)d_in[1];
    const float* emb_g1  = (const float*)d_in[2];
    const float* emb_b1  = (const float*)d_in[3];
    const float* emb_w2  = (const float*)d_in[4];
    const float* emb_g2  = (const float*)d_in[5];
    const float* emb_b2  = (const float*)d_in[6];
    const float* sg1_w1  = (const float*)d_in[7];
    const float* sg1_cb1 = (const float*)d_in[8];
    const float* sg1_g1  = (const float*)d_in[9];
    const float* sg1_b1  = (const float*)d_in[10];
    const float* sg1_w2  = (const float*)d_in[11];
    const float* sg1_cb2 = (const float*)d_in[12];
    const float* sg1_g2  = (const float*)d_in[13];
    const float* sg1_b2  = (const float*)d_in[14];
    const float* sg2_w1  = (const float*)d_in[15];
    const float* sg2_cb1 = (const float*)d_in[16];
    const float* sg2_g1  = (const float*)d_in[17];
    const float* sg2_b1  = (const float*)d_in[18];
    const float* sg2_w2  = (const float*)d_in[19];
    const float* sg2_cb2 = (const float*)d_in[20];
    const float* sg2_g2  = (const float*)d_in[21];
    const float* sg2_b2  = (const float*)d_in[22];
    float* out = (float*)d_out;

    float *xyz, *xyz1, *xyz2, *f0, *f1r, *feat1, *sum, *sq, *ab, *bufA, *bufB;
    int *fps1, *fps2, *knn1, *knn2;
    cudaGetSymbolAddress((void**)&xyz,   g_xyz);
    cudaGetSymbolAddress((void**)&xyz1,  g_xyz1);
    cudaGetSymbolAddress((void**)&xyz2,  g_xyz2);
    cudaGetSymbolAddress((void**)&f0,    g_f0);
    cudaGetSymbolAddress((void**)&f1r,   g_f1r);
    cudaGetSymbolAddress((void**)&feat1, g_feat1);
    cudaGetSymbolAddress((void**)&sum,   g_sum);
    cudaGetSymbolAddress((void**)&sq,    g_sq);
    cudaGetSymbolAddress((void**)&ab,    g_ab);
    cudaGetSymbolAddress((void**)&bufA,  g_bufA);
    cudaGetSymbolAddress((void**)&bufB,  g_bufB);
    cudaGetSymbolAddress((void**)&fps1,  g_fps1);
    cudaGetSymbolAddress((void**)&fps2,  g_fps2);
    cudaGetSymbolAddress((void**)&knn1,  g_knn1);
    cudaGetSymbolAddress((void**)&knn2,  g_knn2);

    // ---- embedding ----
    zero_kernel<<<1, 512>>>(sum, sq, 64);
    emb1_kernel<<<128, 256>>>(x, emb_w1, xyz, f0, sum, sq);
    bn_finalize<<<1, 512>>>(sum, sq, emb_g1, emb_b1, 1.f/32768.f, 64, ab);
    zero_kernel<<<1, 512>>>(sum, sq, 64);
    gemm_bn_kernel<128,64,16,8,4><<<dim3(256, 1), 256>>>(f0, emb_w2, nullptr, ab, f1r,
                                                         32768, 64, 64, sum, sq);
    bn_finalize<<<1, 512>>>(sum, sq, emb_g2, emb_b2, 1.f/32768.f, 64, ab);

    // ---- stage 1 ----
    fps_kernel<<<16, 256>>>(xyz, 2048, 512, fps1, xyz1);
    knn_kernel<<<dim3(64, 16), 256>>>(xyz1, xyz, 512, 2048, knn1);
    gather1_kernel<<<8192, 256>>>(f1r, fps1, knn1, ab, bufA);
    zero_kernel<<<1, 512>>>(sum, sq, 128);
    gemm_bn_kernel<128,128,16,8,8><<<dim3(2048, 1), 256>>>(bufA, sg1_w1, sg1_cb1, nullptr, bufB,
                                                           262144, 128, 128, sum, sq);
    bn_finalize<<<1, 512>>>(sum, sq, sg1_g1, sg1_b1, 1.f/262144.f, 128, ab);
    zero_kernel<<<1, 512>>>(sum, sq, 128);
    gemm_bn_kernel<128,128,16,8,8><<<dim3(2048, 1), 256>>>(bufB, sg1_w2, sg1_cb2, ab, bufA,
                                                           262144, 128, 128, sum, sq);
    bn_finalize<<<1, 512>>>(sum, sq, sg1_g2, sg1_b2, 1.f/262144.f, 128, ab);
    maxk_kernel<<<1048576/256, 256>>>(bufA, ab, feat1, 128);

    // ---- stage 2 ----
    fps_kernel<<<16, 256>>>(xyz1, 512, 256, fps2, xyz2);
    knn_kernel<<<dim3(32, 16), 256>>>(xyz2, xyz1, 256, 512, knn2);
    gather2_kernel<<<4096, 256>>>(feat1, fps2, knn2, bufB);
    zero_kernel<<<1, 512>>>(sum, sq, 512);
    gemm_bn_kernel<128,128,16,8,8><<<dim3(1024, 4), 256>>>(bufB, sg2_w1, sg2_cb1, nullptr, bufA,
                                                           131072, 512, 256, sum, sq);
    bn_finalize<<<1, 512>>>(sum, sq, sg2_g1, sg2_b1, 1.f/131072.f, 512, ab);
    zero_kernel<<<1, 512>>>(sum, sq, 512);
    gemm_bn_kernel<128,128,16,8,8><<<dim3(1024, 4), 256>>>(bufA, sg2_w2, sg2_cb2, ab, bufB,
                                                           131072, 512, 512, sum, sq);
    bn_finalize<<<1, 512>>>(sum, sq, sg2_g2, sg2_b2, 1.f/131072.f, 512, ab);
    final_max_kernel<<<2097152/256, 256>>>(bufB, ab, out);
}